// round 10
// baseline (speedup 1.0000x reference)
#include <cuda_runtime.h>

#define EMB 100
#define BOT 5
#define NT  512                      // 16 warps -> 128-reg budget per thread
#define FULLMASK 0xffffffffu

// One CTA per document row, 512 threads.
// doc = invZ * [ sum_s idf_s*emb_s  +  sum_{dups} (count_s-1)*idf_s*emb_s ]
// Histogram atomics are interleaved INTO the main gather batches: they are
// fire-and-forget until the post-gather barrier, filling LSU idle cycles in
// the gather's L2-latency windows.
__global__ void __launch_bounds__(NT, 1)
doc_model_kernel(const int* __restrict__ x,
                 const float* __restrict__ we,
                 const float* __restrict__ idf,
                 const float* __restrict__ fc1w,
                 const float* __restrict__ fc1b,
                 const float* __restrict__ fc2w,
                 const float* __restrict__ fc2b,
                 float* __restrict__ out,
                 int S, int V)
{
    extern __shared__ unsigned int smem[];
    const int histPad = ((((V + 1) >> 1) + 3) & ~3);
    unsigned int* hist = smem;                    // histPad words (16-bit packed)
    float* stage   = (float*)(hist + histPad);    // 16 warps * 256 floats
    float* partial = stage + 16 * 256;            // 16*EMB
    float* zp      = partial + 16 * EMB;          // 16
    float* doc     = zp + 16;                     // EMB
    float* hv      = doc + EMB;                   // 8

    const int tid  = threadIdx.x;
    const int warp = tid >> 5;
    const int lane = tid & 31;

    // ---- token load first (one LDG.128): warp w owns tokens [128w, 128w+128),
    // lane l holds tokens 128w + 4l + {0..3}. Latency hides behind zeroing.
    const int* xr = x + (long long)blockIdx.x * S;
    const int4 t4 = *(const int4*)(xr + (warp << 7) + (lane << 2));

    // ---- zero histogram (vectorized) ----
    uint4* h4 = (uint4*)hist;
    const uint4 z4 = make_uint4(0u, 0u, 0u, 0u);
    for (int i = tid; i < (histPad >> 2); i += NT) h4[i] = z4;

    // idf gathers: independent of the histogram, issue before the barrier
    const float i0 = __ldg(&idf[t4.x]);
    const float i1 = __ldg(&idf[t4.y]);
    const float i2 = __ldg(&idf[t4.z]);
    const float i3 = __ldg(&idf[t4.w]);

    // ---- stage (byte-offset, idf) pairs for the count-free gather ----
    // 64 float4 entries per warp strip; entry j packs pairs for tokens 2j, 2j+1.
    float4* stW = (float4*)(stage + (warp << 8));
    stW[(lane << 1)]     = make_float4(__int_as_float(t4.x * (EMB * 4)), i0,
                                       __int_as_float(t4.y * (EMB * 4)), i1);
    stW[(lane << 1) + 1] = make_float4(__int_as_float(t4.z * (EMB * 4)), i2,
                                       __int_as_float(t4.w * (EMB * 4)), i3);

    // Z partial (idf only -- no counts needed)
    float z = (i0 + i1) + (i2 + i3);
    #pragma unroll
    for (int o = 16; o; o >>= 1) z += __shfl_xor_sync(FULLMASK, z, o);
    if (lane == 0) zp[warp] = z;

    __syncthreads();   // hist zeroed; stage + zp visible

    // ---- MAIN GATHER: 8 batches x 8 stage entries (= 16 tokens, 16
    // independent LDG.128 per batch). This thread's histogram atomic #b
    // (b < 4) is issued between LDG issue and FMA drain of batch b.
    const bool active = lane < (EMB / 4);   // 25 lanes carry the embedding row
    const int  eoff   = lane << 4;
    const char* web = (const char*)we;
    float4 acc0 = make_float4(0.f, 0.f, 0.f, 0.f);
    float4 acc1 = make_float4(0.f, 0.f, 0.f, 0.f);
    const int tok[4] = { t4.x, t4.y, t4.z, t4.w };

    #pragma unroll
    for (int b = 0; b < 8; b++) {
        float4 q[8];
        #pragma unroll
        for (int j = 0; j < 8; j++) q[j] = stW[(b << 3) + j];

        float4 ev0[8], ev1[8];
        if (active) {
            #pragma unroll
            for (int j = 0; j < 8; j++) {
                ev0[j] = *(const float4*)(web + __float_as_int(q[j].x) + eoff);
                ev1[j] = *(const float4*)(web + __float_as_int(q[j].z) + eoff);
            }
        }

        // fire-and-forget histogram increment (consumed after the barrier)
        if (b < 4) {
            const int tb = tok[b];
            atomicAdd(&hist[tb >> 1], 1u << ((tb & 1) << 4));
        }

        if (active) {
            #pragma unroll
            for (int j = 0; j < 8; j++) {
                acc0.x += q[j].y * ev0[j].x; acc0.y += q[j].y * ev0[j].y;
                acc0.z += q[j].y * ev0[j].z; acc0.w += q[j].y * ev0[j].w;
                acc1.x += q[j].w * ev1[j].x; acc1.y += q[j].w * ev1[j].y;
                acc1.z += q[j].w * ev1[j].z; acc1.w += q[j].w * ev1[j].w;
            }
        }
    }

    __syncthreads();   // all histogram atomics now complete and visible

    float zz = 0.f;
    #pragma unroll
    for (int i = 0; i < 16; i++) zz += zp[i];
    const float invZ = 1.0f / zz;

    // ---- duplicate correction: queue (offset, (count-1)*idf) for count>=2.
    // Expected ~83 duplicated occurrences per ROW (~5 per warp).
    const unsigned n0 = (hist[t4.x >> 1] >> ((t4.x & 1) << 4)) & 0xFFFFu;
    const unsigned n1 = (hist[t4.y >> 1] >> ((t4.y & 1) << 4)) & 0xFFFFu;
    const unsigned n2 = (hist[t4.z >> 1] >> ((t4.z & 1) << 4)) & 0xFFFFu;
    const unsigned n3 = (hist[t4.w >> 1] >> ((t4.w & 1) << 4)) & 0xFFFFu;
    __syncwarp();                                   // strip reuse is now safe

    float2* q2 = (float2*)(stage + (warp << 8));    // capacity 128 entries
    int qlen = 0;
    {
        const unsigned lt = (1u << lane) - 1u;
        unsigned m;
        m = __ballot_sync(FULLMASK, n0 > 1);
        if (n0 > 1) q2[qlen + __popc(m & lt)] =
            make_float2(__int_as_float(t4.x * (EMB * 4)), (float)(n0 - 1) * i0);
        qlen += __popc(m);
        m = __ballot_sync(FULLMASK, n1 > 1);
        if (n1 > 1) q2[qlen + __popc(m & lt)] =
            make_float2(__int_as_float(t4.y * (EMB * 4)), (float)(n1 - 1) * i1);
        qlen += __popc(m);
        m = __ballot_sync(FULLMASK, n2 > 1);
        if (n2 > 1) q2[qlen + __popc(m & lt)] =
            make_float2(__int_as_float(t4.z * (EMB * 4)), (float)(n2 - 1) * i2);
        qlen += __popc(m);
        m = __ballot_sync(FULLMASK, n3 > 1);
        if (n3 > 1) q2[qlen + __popc(m & lt)] =
            make_float2(__int_as_float(t4.w * (EMB * 4)), (float)(n3 - 1) * i3);
        qlen += __popc(m);
    }
    __syncwarp();

    for (int j = 0; j < qlen; j++) {
        const float2 e = q2[j];
        if (active) {
            const float4 ev = *(const float4*)(web + __float_as_int(e.x) + eoff);
            acc0.x += e.y * ev.x; acc0.y += e.y * ev.y;
            acc0.z += e.y * ev.z; acc0.w += e.y * ev.w;
        }
    }

    if (active) {
        acc0.x += acc1.x; acc0.y += acc1.y; acc0.z += acc1.z; acc0.w += acc1.w;
        ((float4*)(partial + warp * EMB))[lane] = acc0;
    }
    __syncthreads();

    // deterministic cross-warp reduction, scaled by invZ
    if (tid < EMB) {
        float d = 0.f;
        #pragma unroll
        for (int w = 0; w < 16; w++) d += partial[w * EMB + tid];
        doc[tid] = d * invZ;
    }
    __syncthreads();

    // ---- tiny MLP 100 -> 5 -> 100 ----
    if (tid < BOT) {
        float h = __ldg(&fc1b[tid]);
        #pragma unroll
        for (int e = 0; e < EMB; e++) h += doc[e] * __ldg(&fc1w[tid * EMB + e]);
        hv[tid] = h;
    }
    __syncthreads();
    if (tid < EMB) {
        float o = __ldg(&fc2b[tid]);
        #pragma unroll
        for (int j = 0; j < BOT; j++) o += hv[j] * __ldg(&fc2w[tid * BOT + j]);
        out[(long long)blockIdx.x * EMB + tid] = o;
    }
}

extern "C" void kernel_launch(void* const* d_in, const int* in_sizes, int n_in,
                              void* d_out, int out_size)
{
    const int*   x    = (const int*)  d_in[0];   // [B,S] int32 token ids
    const float* we   = (const float*)d_in[1];   // [V,EMB]
    const float* idf  = (const float*)d_in[2];   // [V]
    const float* fc1w = (const float*)d_in[3];   // [BOT,EMB]
    const float* fc1b = (const float*)d_in[4];   // [BOT]
    const float* fc2w = (const float*)d_in[5];   // [EMB,BOT]
    const float* fc2b = (const float*)d_in[6];   // [EMB]
    float* out = (float*)d_out;                  // [B,EMB]

    const int V = in_sizes[2];
    const int B = out_size / EMB;
    const int S = in_sizes[0] / B;

    const int histPad = ((((V + 1) >> 1) + 3) & ~3);
    size_t smem_bytes = (size_t)histPad * 4
                      + (size_t)(16 * 256 + 16 * EMB + 16 + EMB + 8) * 4;

    cudaFuncSetAttribute(doc_model_kernel,
                         cudaFuncAttributeMaxDynamicSharedMemorySize,
                         (int)smem_bytes);

    doc_model_kernel<<<B, NT, smem_bytes>>>(x, we, idf, fc1w, fc1b, fc2w, fc2b,
                                            out, S, V);
}